// round 1
// baseline (speedup 1.0000x reference)
#include <cuda_runtime.h>
#include <cstdint>
#include <cstddef>

// ---------------------------------------------------------------------------
// PointSampler: reproduce jax threefry-based masked random permutation sample.
//   x    [B,C,H,W] f32, mask [B,1,H,W] f32, k=4096
//   out  = concat( samples[B,k,C], b_idx[B,k], h_idx[B,k], w_idx[B,k] ) as f32
// ---------------------------------------------------------------------------

#define JAX_PARTITIONABLE 1   // modern jax default; set 0 for legacy threefry path

constexpr int B = 16, C = 256, H = 128, W = 128;
constexpr int L = H * W;        // 16384
constexpr int K = 4096;
constexpr int NBIN = 16385;     // 16384 mantissa-prefix bins + 1 "unmasked" bin
constexpr int SMEM_BYTES = L * 8 + 16386 * 4 + 1024 * 4;  // pairs + hist + scan

__device__ uint64_t g_keys[B * L];   // (mkey<<14)|l per element
__device__ uint32_t g_pos[B * K];    // rank -> flat position
__device__ int      g_counts[B];     // #masked per batch

// ---- jax threefry2x32 (20 rounds) -----------------------------------------
__device__ __forceinline__ void threefry2x32(uint32_t k0, uint32_t k1,
                                             uint32_t x0, uint32_t x1,
                                             uint32_t& o0, uint32_t& o1) {
    uint32_t ks2 = k0 ^ k1 ^ 0x1BD11BDAu;
    x0 += k0; x1 += k1;
#define TF_RND(r) { x0 += x1; x1 = __funnelshift_l(x1, x1, (r)); x1 ^= x0; }
    TF_RND(13) TF_RND(15) TF_RND(26) TF_RND(6)
    x0 += k1;  x1 += ks2 + 1u;
    TF_RND(17) TF_RND(29) TF_RND(16) TF_RND(24)
    x0 += ks2; x1 += k0 + 2u;
    TF_RND(13) TF_RND(15) TF_RND(26) TF_RND(6)
    x0 += k0;  x1 += k1 + 3u;
    TF_RND(17) TF_RND(29) TF_RND(16) TF_RND(24)
    x0 += k1;  x1 += ks2 + 4u;
    TF_RND(13) TF_RND(15) TF_RND(26) TF_RND(6)
    x0 += ks2; x1 += k0 + 5u;
#undef TF_RND
    o0 = x0; o1 = x1;
}

// ---- kernel 0: per-element sort keys (full-chip, ALU-bound) ---------------
__global__ void keys_kernel(const float* __restrict__ mask) {
    int n = blockIdx.x * blockDim.x + threadIdx.x;
    if (n >= B * L) return;
    uint32_t bits;
#if JAX_PARTITIONABLE
    // bits[n] = o0 ^ o1 of threefry(key, (hi32(n)=0, lo32(n)=n))
    uint32_t o0, o1;
    threefry2x32(0u, 42u, 0u, (uint32_t)n, o0, o1);
    bits = o0 ^ o1;
#else
    // legacy: counts iota split in halves, lane i -> (y0 at i, y1 at i+half)
    const uint32_t half = (uint32_t)(B * L) / 2u;
    uint32_t o0, o1;
    if ((uint32_t)n < half) {
        threefry2x32(0u, 42u, (uint32_t)n, (uint32_t)n + half, o0, o1);
        bits = o0;
    } else {
        threefry2x32(0u, 42u, (uint32_t)n - half, (uint32_t)n, o0, o1);
        bits = o1;
    }
#endif
    // uniform(0,1) = bitcast(bits>>9 | 0x3f800000) - 1  -> order == order of (bits>>9)
    bool masked = mask[n] > 0.5f;
    uint32_t mkey = masked ? (bits >> 9) : 0x800000u;   // sentinel sorts after all masked
    uint32_t l = (uint32_t)n & (uint32_t)(L - 1);
    g_keys[n] = (((uint64_t)mkey) << 14) | (uint64_t)l;
}

// ---- kernel 1: per-batch stable rank of the k smallest keys ---------------
__global__ __launch_bounds__(1024, 1) void select_kernel() {
    extern __shared__ unsigned char sm[];
    uint64_t* pairs = (uint64_t*)sm;                       // 16384 * 8
    uint32_t* hist  = (uint32_t*)(sm + (size_t)L * 8);     // 16386 * 4
    uint32_t* part  = (uint32_t*)(sm + (size_t)L * 8 + 16386 * 4);  // 1024 * 4

    const int b = blockIdx.x;
    const int t = threadIdx.x;

    uint64_t keys[16];
#pragma unroll
    for (int i = 0; i < 16; i++)
        keys[i] = g_keys[b * L + t + i * 1024];

    for (int i = t; i < NBIN; i += 1024) hist[i] = 0u;
    __syncthreads();

#pragma unroll
    for (int i = 0; i < 16; i++) {
        uint32_t bin = (uint32_t)(keys[i] >> 23);          // mkey>>9 (or 16384 for unmasked)
        atomicAdd(&hist[bin], 1u);
    }
    __syncthreads();

    // exclusive scan of 16385 bins (16 per thread; thread 1023 takes 17)
    const int start = t * 16;
    const int cnt = (t == 1023) ? 17 : 16;
    uint32_t s = 0;
    for (int i = 0; i < cnt; i++) s += hist[start + i];
    part[t] = s;
    __syncthreads();
    for (int off = 1; off < 1024; off <<= 1) {
        uint32_t v = part[t];
        uint32_t a = (t >= off) ? part[t - off] : 0u;
        __syncthreads();
        part[t] = v + a;
        __syncthreads();
    }
    uint32_t run = (t == 0) ? 0u : part[t - 1];
    for (int i = 0; i < cnt; i++) {
        uint32_t h = hist[start + i];
        hist[start + i] = run;
        run += h;
    }
    __syncthreads();
    if (t == 0) g_counts[b] = (int)hist[16384];            // #masked
    __syncthreads();

    // counting-sort scatter (within-bin order arbitrary; fixed up below)
#pragma unroll
    for (int i = 0; i < 16; i++) {
        uint32_t bin = (uint32_t)(keys[i] >> 23);
        uint32_t slot = atomicAdd(&hist[bin], 1u);
        pairs[slot] = keys[i];
    }
    __syncthreads();

    // final rank = bin base + #smaller within bin (bins avg 1 element)
    for (int sI = t; sI < L; sI += 1024) {
        uint64_t kv = pairs[sI];
        uint32_t mk = (uint32_t)(kv >> 14);
        if (mk >= 0x800000u) continue;                     // unmasked: never selected
        uint32_t bn = (uint32_t)(kv >> 23);
        int g = sI;
        while (g > 0 && (uint32_t)(pairs[g - 1] >> 23) == bn) g--;
        int r = 0;
        for (int u = g; u < L; u++) {
            uint64_t pk = pairs[u];
            if ((uint32_t)(pk >> 23) != bn) break;
            if (pk < kv) r++;
        }
        int rank = g + r;
        if (rank < K) g_pos[b * K + rank] = (uint32_t)(kv & (uint64_t)(L - 1));
    }
}

// ---- kernel 2: gather samples [B,k,C] -------------------------------------
__global__ void gather_kernel(const float* __restrict__ x, float* __restrict__ out) {
    const int b = blockIdx.y;
    const int j0 = blockIdx.x * 16;
    const int c = threadIdx.x;                              // 256 threads
    __shared__ uint32_t sp[16];
    if (c < 16) {
        int j = j0 + c;
        int cb = g_counts[b];
        int eff = (j < cb) ? j : (j % cb);
        sp[c] = g_pos[b * K + eff];
    }
    __syncthreads();
    const float* xb = x + ((size_t)(b * C + c)) * (size_t)L;
    float v[16];
#pragma unroll
    for (int i = 0; i < 16; i++) v[i] = __ldg(&xb[sp[i]]);  // 16 outstanding loads
    float* ob = out + ((size_t)b * K + (size_t)j0) * (size_t)C + c;
#pragma unroll
    for (int i = 0; i < 16; i++) ob[(size_t)i * C] = v[i];  // coalesced stores
}

// ---- kernel 3: (b, h, w) index outputs as f32 -----------------------------
__global__ void idx_kernel(float* __restrict__ out, int out_size) {
    int i = blockIdx.x * blockDim.x + threadIdx.x;
    if (i >= B * K) return;
    int b = i >> 12;
    int j = i & (K - 1);
    int cb = g_counts[b];
    int eff = (j < cb) ? j : (j % cb);
    uint32_t p = g_pos[b * K + eff];
    size_t off = (size_t)B * K * C;
    if ((size_t)out_size >= off + 3u * (size_t)(B * K)) {
        out[off + i] = (float)b;
        out[off + (size_t)(B * K) + i] = (float)(p >> 7);        // h = pos / W
        out[off + 2u * (size_t)(B * K) + i] = (float)(p & (W - 1)); // w = pos % W
    }
}

extern "C" void kernel_launch(void* const* d_in, const int* in_sizes, int n_in,
                              void* d_out, int out_size) {
    const float* x = (const float*)d_in[0];
    // mask is the other B*L-sized f32 input (robust to k being passed or not)
    int mi = n_in - 1;
    for (int i = 1; i < n_in; i++)
        if (in_sizes[i] == B * L) { mi = i; break; }
    const float* mask = (const float*)d_in[mi];
    float* out = (float*)d_out;

    cudaFuncSetAttribute(select_kernel,
                         cudaFuncAttributeMaxDynamicSharedMemorySize, SMEM_BYTES);

    keys_kernel<<<(B * L + 511) / 512, 512>>>(mask);
    select_kernel<<<B, 1024, SMEM_BYTES>>>();
    dim3 gg(K / 16, B);
    gather_kernel<<<gg, 256>>>(x, out);
    idx_kernel<<<(B * K + 255) / 256, 256>>>(out, out_size);
}